// round 6
// baseline (speedup 1.0000x reference)
#include <cuda_runtime.h>
#include <cstdint>
#include <cstddef>

#define Dm   512
#define Bm_  16
#define Sm   4096
#define G3   1536
#define NBLK 128
#define NTHR 256

// Scratch (device globals: allocation-free per harness rules)
__device__ float    g_gi[(size_t)Bm_ * Sm * G3];   // [b][t][1536]
__device__ float    g_rnn[(size_t)Bm_ * Sm * Dm];  // [b][t][512]
__device__ float    g_h[2][Dm * Bm_];              // ping-pong H, [k][b] layout
__device__ unsigned g_flag[NBLK];                  // per-block monotone step flags

__global__ void init_state()
{
    int tid = blockIdx.x * blockDim.x + threadIdx.x;
    if (tid < NBLK) g_flag[tid] = 0u;
    if (tid < Dm * Bm_) g_h[0][tid] = 0.f;
}

// packed fp32x2 fma: d = a*b + d
__device__ __forceinline__ void ffma2(unsigned long long& d,
                                      unsigned long long a,
                                      unsigned long long b)
{
    asm("fma.rn.f32x2 %0, %1, %2, %0;" : "+l"(d) : "l"(a), "l"(b));
}

// LDS.128 of two packed f32x2 pairs at [base + imm]
#define LDSW(w0, w1, sa, IMM) \
    asm("ld.shared.v2.u64 {%0,%1}, [%2+" #IMM "];" : "=l"(w0), "=l"(w1) : "r"(sa))

__device__ __forceinline__ float sigmoid_f(float a)
{
    return __fdividef(1.f, 1.f + __expf(-a));
}
__device__ __forceinline__ float tanh_f(float a)
{
    return __fdividef(2.f, 1.f + __expf(-2.f * a)) - 1.f;
}

// ---------------------------------------------------------------------------
// SGEMM: C[M,N] = A[M,K] @ B[K,N] + bias[N]   (BM=128, BN=64, BK=16)
// ---------------------------------------------------------------------------
__global__ void __launch_bounds__(256) sgemm_bias(
    const float* __restrict__ A, const float* __restrict__ Bmat,
    const float* __restrict__ bias, float* __restrict__ C,
    int M, int N, int K)
{
    __shared__ float As[16][132];
    __shared__ float Bs[16][64];

    const int tid = threadIdx.x;
    const int tx = tid & 15;
    const int ty = tid >> 4;
    const int m0 = blockIdx.y * 128;
    const int n0 = blockIdx.x * 64;

    const int a_row = tid >> 2;
    const int a_kq  = (tid & 3) * 4;

    float acc[8][4];
#pragma unroll
    for (int i = 0; i < 8; ++i)
#pragma unroll
        for (int j = 0; j < 4; ++j) acc[i][j] = 0.f;

    for (int k0 = 0; k0 < K; k0 += 16) {
#pragma unroll
        for (int j = 0; j < 2; ++j) {
            int row = a_row + j * 64;
            float4 v = *(const float4*)(A + (size_t)(m0 + row) * K + k0 + a_kq);
            As[a_kq + 0][row] = v.x;
            As[a_kq + 1][row] = v.y;
            As[a_kq + 2][row] = v.z;
            As[a_kq + 3][row] = v.w;
        }
        {
            float4 v = *(const float4*)(Bmat + (size_t)(k0 + ty) * N + n0 + tx * 4);
            *(float4*)&Bs[ty][tx * 4] = v;
        }
        __syncthreads();
#pragma unroll
        for (int kk = 0; kk < 16; ++kk) {
            float a[8], b[4];
            *(float4*)&a[0] = *(const float4*)&As[kk][ty * 8];
            *(float4*)&a[4] = *(const float4*)&As[kk][ty * 8 + 4];
            *(float4*)&b[0] = *(const float4*)&Bs[kk][tx * 4];
#pragma unroll
            for (int i = 0; i < 8; ++i)
#pragma unroll
                for (int j = 0; j < 4; ++j)
                    acc[i][j] += a[i] * b[j];
        }
        __syncthreads();
    }

    float4 bv = *(const float4*)(bias + n0 + tx * 4);
#pragma unroll
    for (int i = 0; i < 8; ++i) {
        float4 o;
        o.x = acc[i][0] + bv.x;
        o.y = acc[i][1] + bv.y;
        o.z = acc[i][2] + bv.z;
        o.w = acc[i][3] + bv.w;
        *(float4*)(C + (size_t)(m0 + ty * 8 + i) * N + n0 + tx * 4) = o;
    }
}

// ---------------------------------------------------------------------------
// Persistent GRU scan. 128 blocks x 256 threads; block owns 4 h-dims
// (12 Wh cols, duplicated (w,w) pairs in SMEM). FFMA2 k-loop reads H
// directly from global (L2-hot). Atomic-free distributed-flag barrier.
// ---------------------------------------------------------------------------
extern __shared__ float smem_dyn[];

__global__ void __launch_bounds__(NTHR) gru_scan(
    const float* __restrict__ Wh, const float* __restrict__ bhn)
{
    float* wh2 = smem_dyn;                 // [512][24] dup weight pairs
    float* red = smem_dyn + Dm * 24;       // [12][128]

    const int tid = threadIdx.x;
    const int bid = blockIdx.x;
    const int d0  = bid * 4;

    // one-time: load + duplicate Wh column slice
    for (int i = tid; i < Dm * 12; i += NTHR) {
        int k = i / 12, j = i - k * 12;
        int g = j >> 2, jd = j & 3;
        float w = Wh[(size_t)k * G3 + g * Dm + d0 + jd];
        wh2[k * 24 + j * 2 + 0] = w;
        wh2[k * 24 + j * 2 + 1] = w;
    }
    __syncthreads();

    const int warp = tid >> 5, lane = tid & 31;
    const int bp = lane & 7;            // batch pair -> batches 2bp, 2bp+1
    const int kg = lane >> 3;           // 0..3
    const int gd = tid >> 4, gb = tid & 15;   // gate mapping (tid<64)
    float my_bhn = 0.f;
    if (tid < 64) my_bhn = bhn[d0 + gd];

    const unsigned sbase0 = (unsigned)__cvta_generic_to_shared(wh2)
                          + (unsigned)((warp * 64 + kg) * 96);
    const unsigned* myflag = &g_flag[(warp << 5) | lane];

    for (int t = 0; t < Sm; ++t) {
        const float* Hc = g_h[t & 1];
        float* Hn = g_h[(t & 1) ^ 1];

        // gi prefetch (independent of barrier)
        float gir = 0.f, giz = 0.f, gin = 0.f;
        if (tid < 64) {
            const float* gp = g_gi + ((size_t)gb * Sm + t) * G3 + d0 + gd;
            gir = __ldg(gp); giz = __ldg(gp + Dm); gin = __ldg(gp + 2 * Dm);
        }

        // ---- barrier acquire: wait for all 128 flags >= t (warps 0-3 poll) ----
        if (t > 0) {
            if (warp < 4) {
                unsigned v;
                do {
                    asm volatile("ld.relaxed.gpu.u32 %0, [%1];"
                                 : "=r"(v) : "l"(myflag));
                } while (!__all_sync(0xffffffffu, v >= (unsigned)t));
                asm volatile("fence.acq_rel.gpu;" ::: "memory");
            }
            __syncthreads();
        }

        // gate h_old prefetch (overlaps k-loop)
        float hold = 0.f;
        if (tid < 64) hold = __ldg(&Hc[((d0 + gd) << 4) + gb]);

        // ---- packed k-loop: H read directly from global ----
        const unsigned long long* hp =
            (const unsigned long long*)Hc + ((warp * 64 + kg) * 8 + bp);

        unsigned long long acc[12];
#pragma unroll
        for (int j = 0; j < 12; ++j) acc[j] = 0ull;

#pragma unroll
        for (int i = 0; i < 16; ++i) {
            unsigned long long hv = hp[i * 32];      // 4 k stride = 32 u64
            unsigned sa = sbase0 + (unsigned)(i * 384);
            unsigned long long w0, w1, w2, w3, w4, w5;
            LDSW(w0, w1, sa, 0);
            LDSW(w2, w3, sa, 16);
            LDSW(w4, w5, sa, 32);
            ffma2(acc[0], w0, hv);
            ffma2(acc[1], w1, hv);
            ffma2(acc[2], w2, hv);
            ffma2(acc[3], w3, hv);
            ffma2(acc[4], w4, hv);
            ffma2(acc[5], w5, hv);
            LDSW(w0, w1, sa, 48);
            LDSW(w2, w3, sa, 64);
            LDSW(w4, w5, sa, 80);
            ffma2(acc[6],  w0, hv);
            ffma2(acc[7],  w1, hv);
            ffma2(acc[8],  w2, hv);
            ffma2(acc[9],  w3, hv);
            ffma2(acc[10], w4, hv);
            ffma2(acc[11], w5, hv);
        }

        // reduce over kg (lane bits 3,4)
        float aL[12], aH[12];
#pragma unroll
        for (int j = 0; j < 12; ++j) {
            asm("mov.b64 {%0,%1}, %2;" : "=f"(aL[j]), "=f"(aH[j]) : "l"(acc[j]));
            aL[j] += __shfl_xor_sync(0xffffffffu, aL[j], 8);
            aH[j] += __shfl_xor_sync(0xffffffffu, aH[j], 8);
            aL[j] += __shfl_xor_sync(0xffffffffu, aL[j], 16);
            aH[j] += __shfl_xor_sync(0xffffffffu, aH[j], 16);
        }
        if (kg == 0) {
#pragma unroll
            for (int j = 0; j < 12; ++j) {
                float2 v = make_float2(aL[j], aH[j]);
                *(float2*)&red[j * 128 + warp * 16 + (bp << 1)] = v;
            }
        }
        __syncthreads();

        if (tid < 64) {
            float ghr = 0.f, ghz = 0.f, ghn = 0.f;
#pragma unroll
            for (int w = 0; w < 8; ++w) {
                ghr += red[(0 + gd) * 128 + w * 16 + gb];
                ghz += red[(4 + gd) * 128 + w * 16 + gb];
                ghn += red[(8 + gd) * 128 + w * 16 + gb];
            }
            float r = sigmoid_f(gir + ghr);
            float z = sigmoid_f(giz + ghz);
            float n = tanh_f(gin + r * (ghn + my_bhn));
            float hnew = (1.f - z) * n + z * hold;
            Hn[((d0 + gd) << 4) + gb] = hnew;
            g_rnn[((size_t)gb * Sm + t) * Dm + d0 + gd] = hnew;
        }
        __syncthreads();

        // ---- barrier release: publish own flag (no atomics) ----
        if (tid == 0) {
            asm volatile("fence.acq_rel.gpu;" ::: "memory");
            asm volatile("st.relaxed.gpu.u32 [%0], %1;"
                         :: "l"(&g_flag[bid]), "r"((unsigned)(t + 1)) : "memory");
        }
    }
}

// ---------------------------------------------------------------------------
extern "C" void kernel_launch(void* const* d_in, const int* in_sizes, int n_in,
                              void* d_out, int out_size)
{
    const float* x   = (const float*)d_in[0];
    const float* Wi  = (const float*)d_in[1];
    const float* bi  = (const float*)d_in[2];
    const float* Wh  = (const float*)d_in[3];
    const float* bhn = (const float*)d_in[4];
    const float* Wo  = (const float*)d_in[5];
    const float* bo  = (const float*)d_in[6];
    float* out = (float*)d_out;

    void* gi_ptr = nullptr;
    void* rnn_ptr = nullptr;
    cudaGetSymbolAddress(&gi_ptr, g_gi);
    cudaGetSymbolAddress(&rnn_ptr, g_rnn);

    const int smem_bytes = (Dm * 24 + 12 * 128) * (int)sizeof(float); // 55296
    cudaFuncSetAttribute(gru_scan, cudaFuncAttributeMaxDynamicSharedMemorySize, smem_bytes);

    init_state<<<32, 256>>>();

    dim3 g1(G3 / 64, (Bm_ * Sm) / 128);
    sgemm_bias<<<g1, 256>>>(x, Wi, bi, (float*)gi_ptr, Bm_ * Sm, G3, Dm);

    gru_scan<<<NBLK, NTHR, smem_bytes>>>(Wh, bhn);

    dim3 g2(Dm / 64, (Bm_ * Sm) / 128);
    sgemm_bias<<<g2, 256>>>((const float*)rnn_ptr, Wo, bo, out, Bm_ * Sm, Dm, Dm);
}

// round 7
// speedup vs baseline: 1.8680x; 1.8680x over previous
#include <cuda_runtime.h>
#include <cstdint>
#include <cstddef>

#define Dm   512
#define Bm_  16
#define Sm   4096
#define G3   1536
#define NBLK 128
#define NTHR 256
#define NGRP 8
#define GSZ  16

// Scratch (device globals: allocation-free per harness rules)
__device__ float    g_gi[(size_t)Bm_ * Sm * G3];   // [b][t][1536]
__device__ float    g_rnn[(size_t)Bm_ * Sm * Dm];  // [b][t][512]
__device__ float    g_h[2][Dm * Bm_];              // ping-pong H, [k][b] layout
__device__ unsigned g_grp[NGRP * 32];              // group counters, 128B stride
__device__ unsigned g_root[32];                    // root counter (padded line)
__device__ unsigned g_step[32];                    // published step (padded line)

__global__ void init_state()
{
    int tid = blockIdx.x * blockDim.x + threadIdx.x;
    if (tid < NGRP * 32) g_grp[tid] = 0u;
    if (tid < 32) { g_root[tid] = 0u; g_step[tid] = 0u; }
    if (tid < Dm * Bm_) g_h[0][tid] = 0.f;
}

__device__ __forceinline__ unsigned ld_acq(const unsigned* p)
{
    unsigned v;
    asm volatile("ld.acquire.gpu.u32 %0, [%1];" : "=r"(v) : "l"(p) : "memory");
    return v;
}
__device__ __forceinline__ unsigned atom_inc_acqrel(unsigned* p)
{
    unsigned v;
    asm volatile("atom.acq_rel.gpu.global.add.u32 %0, [%1], 1;"
                 : "=r"(v) : "l"(p) : "memory");
    return v;
}

// packed fp32x2 fma: d = a*b + d
__device__ __forceinline__ void ffma2(unsigned long long& d,
                                      unsigned long long a,
                                      unsigned long long b)
{
    asm("fma.rn.f32x2 %0, %1, %2, %0;" : "+l"(d) : "l"(a), "l"(b));
}

__device__ __forceinline__ void ld_s_v2u64(unsigned long long& a,
                                           unsigned long long& b,
                                           unsigned saddr)
{
    asm("ld.shared.v2.u64 {%0,%1}, [%2];" : "=l"(a), "=l"(b) : "r"(saddr));
}

// ---------------------------------------------------------------------------
// SGEMM: C[M,N] = A[M,K] @ B[K,N] + bias[N]   (BM=128, BN=64, BK=16)
// ---------------------------------------------------------------------------
__global__ void __launch_bounds__(256) sgemm_bias(
    const float* __restrict__ A, const float* __restrict__ Bmat,
    const float* __restrict__ bias, float* __restrict__ C,
    int M, int N, int K)
{
    __shared__ float As[16][132];
    __shared__ float Bs[16][64];

    const int tid = threadIdx.x;
    const int tx = tid & 15;
    const int ty = tid >> 4;
    const int m0 = blockIdx.y * 128;
    const int n0 = blockIdx.x * 64;

    const int a_row = tid >> 2;
    const int a_kq  = (tid & 3) * 4;

    float acc[8][4];
#pragma unroll
    for (int i = 0; i < 8; ++i)
#pragma unroll
        for (int j = 0; j < 4; ++j) acc[i][j] = 0.f;

    for (int k0 = 0; k0 < K; k0 += 16) {
#pragma unroll
        for (int j = 0; j < 2; ++j) {
            int row = a_row + j * 64;
            float4 v = *(const float4*)(A + (size_t)(m0 + row) * K + k0 + a_kq);
            As[a_kq + 0][row] = v.x;
            As[a_kq + 1][row] = v.y;
            As[a_kq + 2][row] = v.z;
            As[a_kq + 3][row] = v.w;
        }
        {
            float4 v = *(const float4*)(Bmat + (size_t)(k0 + ty) * N + n0 + tx * 4);
            *(float4*)&Bs[ty][tx * 4] = v;
        }
        __syncthreads();
#pragma unroll
        for (int kk = 0; kk < 16; ++kk) {
            float a[8], b[4];
            *(float4*)&a[0] = *(const float4*)&As[kk][ty * 8];
            *(float4*)&a[4] = *(const float4*)&As[kk][ty * 8 + 4];
            *(float4*)&b[0] = *(const float4*)&Bs[kk][tx * 4];
#pragma unroll
            for (int i = 0; i < 8; ++i)
#pragma unroll
                for (int j = 0; j < 4; ++j)
                    acc[i][j] += a[i] * b[j];
        }
        __syncthreads();
    }

    float4 bv = *(const float4*)(bias + n0 + tx * 4);
#pragma unroll
    for (int i = 0; i < 8; ++i) {
        float4 o;
        o.x = acc[i][0] + bv.x;
        o.y = acc[i][1] + bv.y;
        o.z = acc[i][2] + bv.z;
        o.w = acc[i][3] + bv.w;
        *(float4*)(C + (size_t)(m0 + ty * 8 + i) * N + n0 + tx * 4) = o;
    }
}

// ---------------------------------------------------------------------------
// Persistent GRU scan, FFMA2 inner loop (R5 datapath), two-level tree barrier.
// 128 blocks x 256 threads; block owns 4 h-dims (12 Wh cols, dup (w,w) pairs).
// ---------------------------------------------------------------------------
extern __shared__ float smem_dyn[];

__global__ void __launch_bounds__(NTHR, 1) gru_scan(
    const float* __restrict__ Wh, const float* __restrict__ bhn)
{
    float* wh2 = smem_dyn;                       // [512][24]  dup weights
    float* h_s = smem_dyn + Dm * 24;             // [512][16]
    float* red = smem_dyn + Dm * 24 + Dm * 16;   // [12][128]

    const int tid = threadIdx.x;
    const int bid = blockIdx.x;
    const int d0  = bid * 4;

    // one-time: load + duplicate Wh column slice
    for (int i = tid; i < Dm * 12; i += NTHR) {
        int k = i / 12, j = i - k * 12;
        int g = j >> 2, jd = j & 3;
        float w = Wh[(size_t)k * G3 + g * Dm + d0 + jd];
        wh2[k * 24 + j * 2 + 0] = w;
        wh2[k * 24 + j * 2 + 1] = w;
    }

    const int warp = tid >> 5, lane = tid & 31;
    const int bp = lane & 7;           // batch pair -> batches 2bp, 2bp+1
    const int kg = lane >> 3;          // 0..3
    const int gd = tid >> 4, gb = tid & 15;   // gate mapping (tid<64)
    float my_bhn = 0.f;
    if (tid < 64) my_bhn = bhn[d0 + gd];

    const unsigned wh2_base = (unsigned)__cvta_generic_to_shared(wh2);
    unsigned* grp_cnt = &g_grp[(bid >> 4) * 32];

    for (int t = 0; t < Sm; ++t) {
        const float* Hc = g_h[t & 1];
        float* Hn = g_h[(t & 1) ^ 1];

        // prefetch input-side gates (DRAM latency covered by k-loop)
        float gir = 0.f, giz = 0.f, gin = 0.f;
        if (tid < 64) {
            const float* gp = g_gi + ((size_t)gb * Sm + t) * G3 + d0 + gd;
            gir = __ldg(gp); giz = __ldg(gp + Dm); gin = __ldg(gp + 2 * Dm);
        }

        // load H state (coalesced)
#pragma unroll
        for (int i = 0; i < 8; ++i) {
            int idx = (tid + i * NTHR) << 2;
            *(float4*)&h_s[idx] = *(const float4*)&Hc[idx];
        }
        __syncthreads();

        // packed k-loop: 16 k per lane, 12 col-accumulators x 2 batches
        unsigned long long acc[12];
#pragma unroll
        for (int j = 0; j < 12; ++j) acc[j] = 0ull;

#pragma unroll 4
        for (int i = 0; i < 16; ++i) {
            int k = (warp << 6) + (i << 2) + kg;
            unsigned long long hv =
                *(const unsigned long long*)&h_s[(k << 4) + (bp << 1)];
            unsigned saddr = wh2_base + (unsigned)(k * 96);
            unsigned long long w0, w1, w2, w3, w4, w5;
            ld_s_v2u64(w0, w1, saddr);
            ld_s_v2u64(w2, w3, saddr + 16);
            ld_s_v2u64(w4, w5, saddr + 32);
            ffma2(acc[0],  w0, hv);
            ffma2(acc[1],  w1, hv);
            ffma2(acc[2],  w2, hv);
            ffma2(acc[3],  w3, hv);
            ffma2(acc[4],  w4, hv);
            ffma2(acc[5],  w5, hv);
            ld_s_v2u64(w0, w1, saddr + 48);
            ld_s_v2u64(w2, w3, saddr + 64);
            ld_s_v2u64(w4, w5, saddr + 80);
            ffma2(acc[6],  w0, hv);
            ffma2(acc[7],  w1, hv);
            ffma2(acc[8],  w2, hv);
            ffma2(acc[9],  w3, hv);
            ffma2(acc[10], w4, hv);
            ffma2(acc[11], w5, hv);
        }

        // reduce over kg (lane bits 3,4), then kg==0 lanes write partials
        float aL[12], aH[12];
#pragma unroll
        for (int j = 0; j < 12; ++j) {
            asm("mov.b64 {%0,%1}, %2;" : "=f"(aL[j]), "=f"(aH[j]) : "l"(acc[j]));
            aL[j] += __shfl_xor_sync(0xffffffffu, aL[j], 8);
            aH[j] += __shfl_xor_sync(0xffffffffu, aH[j], 8);
            aL[j] += __shfl_xor_sync(0xffffffffu, aL[j], 16);
            aH[j] += __shfl_xor_sync(0xffffffffu, aH[j], 16);
        }
        if (kg == 0) {
#pragma unroll
            for (int j = 0; j < 12; ++j) {
                float2 v = make_float2(aL[j], aH[j]);
                *(float2*)&red[j * 128 + warp * 16 + (bp << 1)] = v;
            }
        }
        __syncthreads();

        if (tid < 64) {
            float ghr = 0.f, ghz = 0.f, ghn = 0.f;
#pragma unroll
            for (int w = 0; w < 8; ++w) {
                ghr += red[(0 + gd) * 128 + w * 16 + gb];
                ghz += red[(4 + gd) * 128 + w * 16 + gb];
                ghn += red[(8 + gd) * 128 + w * 16 + gb];
            }
            float r = 1.f / (1.f + __expf(-(gir + ghr)));
            float z = 1.f / (1.f + __expf(-(giz + ghz)));
            float n = tanhf(gin + r * (ghn + my_bhn));
            float hold = h_s[((d0 + gd) << 4) + gb];
            float hnew = (1.f - z) * n + z * hold;
            Hn[((d0 + gd) << 4) + gb] = hnew;
            g_rnn[((size_t)gb * Sm + t) * Dm + d0 + gd] = hnew;
        }
        __syncthreads();

        // ---- two-level tree barrier (monotone counters, acq_rel chain) ----
        if (tid == 0) {
            unsigned r = atom_inc_acqrel(grp_cnt);
            if (r == (unsigned)(GSZ * (t + 1) - 1)) {
                unsigned r2 = atom_inc_acqrel(&g_root[0]);
                if (r2 == (unsigned)(NGRP * (t + 1) - 1)) {
                    asm volatile("st.release.gpu.u32 [%0], %1;"
                                 :: "l"(&g_step[0]), "r"((unsigned)(t + 1))
                                 : "memory");
                }
            }
            while (ld_acq(&g_step[0]) < (unsigned)(t + 1)) { }
        }
        __syncthreads();
    }
}

// ---------------------------------------------------------------------------
extern "C" void kernel_launch(void* const* d_in, const int* in_sizes, int n_in,
                              void* d_out, int out_size)
{
    const float* x   = (const float*)d_in[0];
    const float* Wi  = (const float*)d_in[1];
    const float* bi  = (const float*)d_in[2];
    const float* Wh  = (const float*)d_in[3];
    const float* bhn = (const float*)d_in[4];
    const float* Wo  = (const float*)d_in[5];
    const float* bo  = (const float*)d_in[6];
    float* out = (float*)d_out;

    void* gi_ptr = nullptr;
    void* rnn_ptr = nullptr;
    cudaGetSymbolAddress(&gi_ptr, g_gi);
    cudaGetSymbolAddress(&rnn_ptr, g_rnn);

    const int smem_bytes = (Dm * 24 + Dm * 16 + 12 * 128) * (int)sizeof(float); // 88064
    cudaFuncSetAttribute(gru_scan, cudaFuncAttributeMaxDynamicSharedMemorySize, smem_bytes);

    init_state<<<32, 256>>>();

    dim3 g1(G3 / 64, (Bm_ * Sm) / 128);
    sgemm_bias<<<g1, 256>>>(x, Wi, bi, (float*)gi_ptr, Bm_ * Sm, G3, Dm);

    gru_scan<<<NBLK, NTHR, smem_bytes>>>(Wh, bhn);

    dim3 g2(Dm / 64, (Bm_ * Sm) / 128);
    sgemm_bias<<<g2, 256>>>((const float*)rnn_ptr, Wo, bo, out, Bm_ * Sm, Dm, Dm);
}

// round 9
// speedup vs baseline: 2.6128x; 1.3987x over previous
#include <cuda_runtime.h>
#include <cstdint>
#include <cstddef>

#define Dm   512
#define Bm_  16
#define Sm   4096
#define G3   1536
#define NGRP 4           // independent scan groups (4 batches each)
#define GCTA 32          // CTAs per group
#define BPG  4           // batches per group
#define DPC  16          // h-dims per CTA
#define NBLK (NGRP * GCTA)
#define NTHR 256
#define WS_STRIDE_F 60   // 240B row stride for weight smem (pad vs bank conflicts)

// Scratch (device globals: allocation-free per harness rules)
__device__ float    g_gi[(size_t)Bm_ * Sm * G3];   // [b][t][1536]
__device__ float    g_rnn[(size_t)Bm_ * Sm * Dm];  // [b][t][512]
__device__ float    g_h[2][NGRP][Dm][BPG];         // ping-pong H per group
__device__ unsigned g_cnt[NGRP * 32];              // per-group counters, 128B apart

__global__ void init_state()
{
    int tid = blockIdx.x * blockDim.x + threadIdx.x;
    if (tid < NGRP * 32) g_cnt[tid] = 0u;
    if (tid < NGRP * Dm * BPG) ((float*)g_h)[tid] = 0.f;   // zero g_h[0]
}

__device__ __forceinline__ unsigned ld_acq(const unsigned* p)
{
    unsigned v;
    asm volatile("ld.acquire.gpu.u32 %0, [%1];" : "=r"(v) : "l"(p) : "memory");
    return v;
}

// packed fp32x2 fma: d = a*b + d
__device__ __forceinline__ void ffma2(unsigned long long& d,
                                      unsigned long long a,
                                      unsigned long long b)
{
    asm("fma.rn.f32x2 %0, %1, %2, %0;" : "+l"(d) : "l"(a), "l"(b));
}

// ---------------------------------------------------------------------------
// SGEMM: C[M,N] = A[M,K] @ B[K,N] + bias[N]   (BM=128, BN=64, BK=16)
// ---------------------------------------------------------------------------
__global__ void __launch_bounds__(256) sgemm_bias(
    const float* __restrict__ A, const float* __restrict__ Bmat,
    const float* __restrict__ bias, float* __restrict__ C,
    int M, int N, int K)
{
    __shared__ float As[16][132];
    __shared__ float Bs[16][64];

    const int tid = threadIdx.x;
    const int tx = tid & 15;
    const int ty = tid >> 4;
    const int m0 = blockIdx.y * 128;
    const int n0 = blockIdx.x * 64;

    const int a_row = tid >> 2;
    const int a_kq  = (tid & 3) * 4;

    float acc[8][4];
#pragma unroll
    for (int i = 0; i < 8; ++i)
#pragma unroll
        for (int j = 0; j < 4; ++j) acc[i][j] = 0.f;

    for (int k0 = 0; k0 < K; k0 += 16) {
#pragma unroll
        for (int j = 0; j < 2; ++j) {
            int row = a_row + j * 64;
            float4 v = *(const float4*)(A + (size_t)(m0 + row) * K + k0 + a_kq);
            As[a_kq + 0][row] = v.x;
            As[a_kq + 1][row] = v.y;
            As[a_kq + 2][row] = v.z;
            As[a_kq + 3][row] = v.w;
        }
        {
            float4 v = *(const float4*)(Bmat + (size_t)(k0 + ty) * N + n0 + tx * 4);
            *(float4*)&Bs[ty][tx * 4] = v;
        }
        __syncthreads();
#pragma unroll
        for (int kk = 0; kk < 16; ++kk) {
            float a[8], b[4];
            *(float4*)&a[0] = *(const float4*)&As[kk][ty * 8];
            *(float4*)&a[4] = *(const float4*)&As[kk][ty * 8 + 4];
            *(float4*)&b[0] = *(const float4*)&Bs[kk][tx * 4];
#pragma unroll
            for (int i = 0; i < 8; ++i)
#pragma unroll
                for (int j = 0; j < 4; ++j)
                    acc[i][j] += a[i] * b[j];
        }
        __syncthreads();
    }

    float4 bv = *(const float4*)(bias + n0 + tx * 4);
#pragma unroll
    for (int i = 0; i < 8; ++i) {
        float4 o;
        o.x = acc[i][0] + bv.x;
        o.y = acc[i][1] + bv.y;
        o.z = acc[i][2] + bv.z;
        o.w = acc[i][3] + bv.w;
        *(float4*)(C + (size_t)(m0 + ty * 8 + i) * N + n0 + tx * 4) = o;
    }
}

// ---------------------------------------------------------------------------
// Persistent GRU scan: 4 independent groups of 32 CTAs (4 batches/group).
// CTA owns 16 h-dims (48 Wh cols as float2 pairs, no dup, 120KB SMEM).
// H duplicated (h,h) in SMEM; FFMA2 inner loop; per-group R5-style barrier.
// ---------------------------------------------------------------------------
extern __shared__ float smem_dyn[];

__global__ void __launch_bounds__(NTHR, 1) gru_scan(
    const float* __restrict__ Wh, const float* __restrict__ bhn)
{
    float* ws = smem_dyn;                                   // [512][60] (24 f2 used)
    unsigned long long* h2 = (unsigned long long*)(smem_dyn + Dm * WS_STRIDE_F); // [512][4]
    float2* red = (float2*)(smem_dyn + Dm * WS_STRIDE_F + Dm * 8);               // [24][4][8]

    const int tid = threadIdx.x;
    const int bid = blockIdx.x;
    const int grp = bid >> 5;
    const int cid = bid & 31;
    const int d0  = cid * DPC;
    const int b0  = grp * BPG;

    // one-time: load 48 Wh columns as 24 float2 col-pairs per k
    for (int i = tid; i < Dm * 24; i += NTHR) {
        int k = i / 24, cp = i - k * 24;
        int gate = cp >> 3, p = cp & 7;
        const float* src = Wh + (size_t)k * G3 + gate * Dm + d0 + 2 * p;
        *(float2*)&ws[k * WS_STRIDE_F + cp * 2] = make_float2(src[0], src[1]);
    }

    const int warp = tid >> 5, lane = tid & 31;
    const int cpg = lane >> 3;          // 0..3 : 6 col-pairs each
    const int b   = (lane >> 1) & 3;    // 0..3 : batch within group
    const int kg  = lane & 1;           // 0..1 : k parity
    const int kbase = warp * 64;

    const int dloc = tid >> 2, gb = tid & 3;   // gate mapping (tid<64)
    float my_bhn = 0.f;
    if (tid < 64) my_bhn = bhn[d0 + dloc];

    const char* ws_ptr = (const char*)ws + (size_t)(kbase + kg) * 240 + cpg * 48;
    const char* h2_ptr = (const char*)h2 + (size_t)(kbase + kg) * 32 + b * 8;

    unsigned* cnt = &g_cnt[grp * 32];
    unsigned target = 0;

    for (int t = 0; t < Sm; ++t) {
        const float* Hc = &g_h[t & 1][grp][0][0];
        float* Hn = &g_h[(t & 1) ^ 1][grp][0][0];

        // gi prefetch (gate threads; consumed late)
        float gir = 0.f, giz = 0.f, gin = 0.f;
        if (tid < 64) {
            const float* gp = g_gi + ((size_t)(b0 + gb) * Sm + t) * G3 + d0 + dloc;
            gir = __ldg(gp); giz = __ldg(gp + Dm); gin = __ldg(gp + 2 * Dm);
        }
        float hold = 0.f;
        if (tid < 64) hold = __ldcg(&Hc[(d0 + dloc) * BPG + gb]);

        // fill duplicated H (2048 floats, coalesced .cg loads)
#pragma unroll
        for (int j = 0; j < 8; ++j) {
            int idx = tid + j * NTHR;
            float v = __ldcg(&Hc[idx]);
            int k = idx >> 2, bb = idx & 3;
            float2 dup = make_float2(v, v);
            h2[(size_t)k * 4 + bb] = *(unsigned long long*)&dup;
        }
        __syncthreads();

        // packed k-loop: 32 iters, 6 col-pairs x 1 batch, k = kbase + 2i + kg
        unsigned long long acc[6];
#pragma unroll
        for (int j = 0; j < 6; ++j) acc[j] = 0ull;

#pragma unroll 8
        for (int i = 0; i < 32; ++i) {
            unsigned long long hv =
                *(const unsigned long long*)(h2_ptr + (size_t)i * 64);
            const char* wp = ws_ptr + (size_t)i * 480;
            ulonglong2 wa = *(const ulonglong2*)(wp + 0);
            ulonglong2 wb = *(const ulonglong2*)(wp + 16);
            ulonglong2 wc = *(const ulonglong2*)(wp + 32);
            ffma2(acc[0], wa.x, hv);
            ffma2(acc[1], wa.y, hv);
            ffma2(acc[2], wb.x, hv);
            ffma2(acc[3], wb.y, hv);
            ffma2(acc[4], wc.x, hv);
            ffma2(acc[5], wc.y, hv);
        }

        // reduce over kg (xor 1), kg==0 lanes write (c0,c1) partials
        float aL[6], aH[6];
#pragma unroll
        for (int j = 0; j < 6; ++j) {
            asm("mov.b64 {%0,%1}, %2;" : "=f"(aL[j]), "=f"(aH[j]) : "l"(acc[j]));
            aL[j] += __shfl_xor_sync(0xffffffffu, aL[j], 1);
            aH[j] += __shfl_xor_sync(0xffffffffu, aH[j], 1);
        }
        if (kg == 0) {
#pragma unroll
            for (int j = 0; j < 6; ++j) {
                int cp = cpg * 6 + j;
                red[(cp * 4 + b) * 8 + warp] = make_float2(aL[j], aH[j]);
            }
        }
        __syncthreads();

        if (tid < 64) {
            float gh[3];
#pragma unroll
            for (int g3 = 0; g3 < 3; ++g3) {
                int cp = g3 * 8 + (dloc >> 1);
                float s = 0.f;
#pragma unroll
                for (int w = 0; w < 8; ++w) {
                    float2 v = red[(cp * 4 + gb) * 8 + w];
                    s += (dloc & 1) ? v.y : v.x;
                }
                gh[g3] = s;
            }
            float r = 1.f / (1.f + __expf(-(gir + gh[0])));
            float z = 1.f / (1.f + __expf(-(giz + gh[1])));
            float n = tanhf(gin + r * (gh[2] + my_bhn));
            float hnew = (1.f - z) * n + z * hold;
            Hn[(d0 + dloc) * BPG + gb] = hnew;
            g_rnn[((size_t)(b0 + gb) * Sm + t) * Dm + d0 + dloc] = hnew;
        }
        __syncthreads();

        // per-group barrier: single monotone counter + poll (R5 mechanism)
        target += GCTA;
        if (tid == 0) {
            __threadfence();
            atomicAdd(cnt, 1u);
            while (ld_acq(cnt) < target) { }
        }
        __syncthreads();
    }
}

// ---------------------------------------------------------------------------
extern "C" void kernel_launch(void* const* d_in, const int* in_sizes, int n_in,
                              void* d_out, int out_size)
{
    const float* x   = (const float*)d_in[0];
    const float* Wi  = (const float*)d_in[1];
    const float* bi  = (const float*)d_in[2];
    const float* Wh  = (const float*)d_in[3];
    const float* bhn = (const float*)d_in[4];
    const float* Wo  = (const float*)d_in[5];
    const float* bo  = (const float*)d_in[6];
    float* out = (float*)d_out;

    void* gi_ptr = nullptr;
    void* rnn_ptr = nullptr;
    cudaGetSymbolAddress(&gi_ptr, g_gi);
    cudaGetSymbolAddress(&rnn_ptr, g_rnn);

    // ws 122880 + h2 16384 + red 6144 = 145408 bytes
    const int smem_bytes = Dm * WS_STRIDE_F * 4 + Dm * 4 * 8 + 24 * 4 * 8 * 8;
    cudaFuncSetAttribute(gru_scan, cudaFuncAttributeMaxDynamicSharedMemorySize, smem_bytes);

    init_state<<<32, 256>>>();

    dim3 g1(G3 / 64, (Bm_ * Sm) / 128);
    sgemm_bias<<<g1, 256>>>(x, Wi, bi, (float*)gi_ptr, Bm_ * Sm, G3, Dm);

    gru_scan<<<NBLK, NTHR, smem_bytes>>>(Wh, bhn);

    dim3 g2(Dm / 64, (Bm_ * Sm) / 128);
    sgemm_bias<<<g2, 256>>>((const float*)rnn_ptr, Wo, bo, out, Bm_ * Sm, Dm, Dm);
}

// round 10
// speedup vs baseline: 3.2103x; 1.2287x over previous
#include <cuda_runtime.h>
#include <cstdint>
#include <cstddef>

#define Dm   512
#define Bm_  16
#define Sm   4096
#define G3   1536
#define NGRP 4           // independent scan groups (4 batches each)
#define GCTA 32          // CTAs per group
#define BPG  4           // batches per group
#define DPC  16          // h-dims per CTA (48 Wh columns)
#define NBLK (NGRP * GCTA)
#define NTHR 256

// Scratch (device globals: allocation-free per harness rules)
__device__ float    g_gi[(size_t)Bm_ * Sm * G3];   // [b][t][1536]
__device__ float    g_rnn[(size_t)Bm_ * Sm * Dm];  // [b][t][512]
__device__ float    g_h[2][NGRP][Dm][BPG];         // ping-pong H per group
__device__ unsigned g_cnt[NGRP * 32];              // per-group counters, 128B apart

__global__ void init_state()
{
    int tid = blockIdx.x * blockDim.x + threadIdx.x;
    if (tid < NGRP * 32) g_cnt[tid] = 0u;
    if (tid < NGRP * Dm * BPG) ((float*)g_h)[tid] = 0.f;   // zero g_h[0]
}

__device__ __forceinline__ unsigned ld_acq(const unsigned* p)
{
    unsigned v;
    asm volatile("ld.acquire.gpu.u32 %0, [%1];" : "=r"(v) : "l"(p) : "memory");
    return v;
}

// pack (w,w) once, then two packed fp32x2 FMAs into separate accumulators
__device__ __forceinline__ void ffma2_dual(unsigned long long& dA,
                                           unsigned long long& dB,
                                           float w,
                                           unsigned long long hA,
                                           unsigned long long hB)
{
    unsigned long long wd;
    asm("mov.b64 %0, {%1, %1};" : "=l"(wd) : "f"(w));
    asm("fma.rn.f32x2 %0, %1, %2, %0;" : "+l"(dA) : "l"(wd), "l"(hA));
    asm("fma.rn.f32x2 %0, %1, %2, %0;" : "+l"(dB) : "l"(wd), "l"(hB));
}

// ---------------------------------------------------------------------------
// SGEMM: C[M,N] = A[M,K] @ B[K,N] + bias[N]   (BM=128, BN=64, BK=16)
// ---------------------------------------------------------------------------
__global__ void __launch_bounds__(256) sgemm_bias(
    const float* __restrict__ A, const float* __restrict__ Bmat,
    const float* __restrict__ bias, float* __restrict__ C,
    int M, int N, int K)
{
    __shared__ float As[16][132];
    __shared__ float Bs[16][64];

    const int tid = threadIdx.x;
    const int tx = tid & 15;
    const int ty = tid >> 4;
    const int m0 = blockIdx.y * 128;
    const int n0 = blockIdx.x * 64;

    const int a_row = tid >> 2;
    const int a_kq  = (tid & 3) * 4;

    float acc[8][4];
#pragma unroll
    for (int i = 0; i < 8; ++i)
#pragma unroll
        for (int j = 0; j < 4; ++j) acc[i][j] = 0.f;

    for (int k0 = 0; k0 < K; k0 += 16) {
#pragma unroll
        for (int j = 0; j < 2; ++j) {
            int row = a_row + j * 64;
            float4 v = *(const float4*)(A + (size_t)(m0 + row) * K + k0 + a_kq);
            As[a_kq + 0][row] = v.x;
            As[a_kq + 1][row] = v.y;
            As[a_kq + 2][row] = v.z;
            As[a_kq + 3][row] = v.w;
        }
        {
            float4 v = *(const float4*)(Bmat + (size_t)(k0 + ty) * N + n0 + tx * 4);
            *(float4*)&Bs[ty][tx * 4] = v;
        }
        __syncthreads();
#pragma unroll
        for (int kk = 0; kk < 16; ++kk) {
            float a[8], b[4];
            *(float4*)&a[0] = *(const float4*)&As[kk][ty * 8];
            *(float4*)&a[4] = *(const float4*)&As[kk][ty * 8 + 4];
            *(float4*)&b[0] = *(const float4*)&Bs[kk][tx * 4];
#pragma unroll
            for (int i = 0; i < 8; ++i)
#pragma unroll
                for (int j = 0; j < 4; ++j)
                    acc[i][j] += a[i] * b[j];
        }
        __syncthreads();
    }

    float4 bv = *(const float4*)(bias + n0 + tx * 4);
#pragma unroll
    for (int i = 0; i < 8; ++i) {
        float4 o;
        o.x = acc[i][0] + bv.x;
        o.y = acc[i][1] + bv.y;
        o.z = acc[i][2] + bv.z;
        o.w = acc[i][3] + bv.w;
        *(float4*)(C + (size_t)(m0 + ty * 8 + i) * N + n0 + tx * 4) = o;
    }
}

// ---------------------------------------------------------------------------
// Persistent GRU scan: weights live in REGISTERS (96 floats/thread) for the
// whole sequence; SMEM carries only H (8KB) + reduction partials (6KB).
// 4 independent groups x 32 CTAs; CTA owns 16 dims x 4 batches.
// warp (8) <-> 6 columns of 48; lane <-> k-slice {lane + 32j}.
// ---------------------------------------------------------------------------
__global__ void __launch_bounds__(NTHR, 1) gru_scan(
    const float* __restrict__ Wh, const float* __restrict__ bhn)
{
    __shared__ float2 hA[Dm];            // (h[b0], h[b1])[k]
    __shared__ float2 hB[Dm];            // (h[b2], h[b3])[k]
    __shared__ float  red[48 * BPG * 8]; // [cc][b][8] 8-way partials

    const int tid = threadIdx.x;
    const int bid = blockIdx.x;
    const int grp = bid >> 5;
    const int cid = bid & 31;
    const int d0  = cid * DPC;
    const int b0  = grp * BPG;

    const int warp = tid >> 5, lane = tid & 31;

    // ---- one-time: load this thread's 96 weights into registers ----
    // col cc = 6*warp + i  ->  gate = cc/16, dim = cc%16 ; k = lane + 32*j
    float w[6][16];
#pragma unroll
    for (int i = 0; i < 6; ++i) {
        int cc = 6 * warp + i;
        int gate = cc >> 4, dim = cc & 15;
        const float* wp = Wh + (size_t)gate * Dm + d0 + dim + (size_t)lane * G3;
#pragma unroll
        for (int j = 0; j < 16; ++j)
            w[i][j] = __ldg(wp + (size_t)j * 32 * G3);
    }

    const int dloc = tid >> 2, gb = tid & 3;   // gate mapping (tid<64)
    float my_bhn = 0.f;
    if (tid < 64) my_bhn = bhn[d0 + dloc];

    unsigned* cnt = &g_cnt[grp * 32];
    unsigned target = 0;

    for (int t = 0; t < Sm; ++t) {
        const float* Hc = &g_h[t & 1][grp][0][0];
        float* Hn = &g_h[(t & 1) ^ 1][grp][0][0];

        // gi prefetch (independent of barrier)
        float gir = 0.f, giz = 0.f, gin = 0.f;
        float hold = 0.f;
        if (tid < 64) {
            const float* gp = g_gi + ((size_t)(b0 + gb) * Sm + t) * G3 + d0 + dloc;
            gir = __ldg(gp); giz = __ldg(gp + Dm); gin = __ldg(gp + 2 * Dm);
            hold = __ldcg(&Hc[(d0 + dloc) * BPG + gb]);  // own dims: safe pre-fill
        }

        // ---- fill hA/hB (deinterleave global [k][4]) ----
#pragma unroll
        for (int r = 0; r < 2; ++r) {
            int k = tid + r * NTHR;
            float4 v = *(const float4*)&Hc[k * BPG];   // fresh: L2 via volatile-ish
            float4 vv;
            asm volatile("ld.global.cg.v4.f32 {%0,%1,%2,%3}, [%4];"
                         : "=f"(vv.x), "=f"(vv.y), "=f"(vv.z), "=f"(vv.w)
                         : "l"(&Hc[k * BPG]));
            (void)v;
            hA[k] = make_float2(vv.x, vv.y);
            hB[k] = make_float2(vv.z, vv.w);
        }
        __syncthreads();

        // ---- k-loop: registers x SMEM-h, FFMA2 ----
        unsigned long long accA[6], accB[6];
#pragma unroll
        for (int i = 0; i < 6; ++i) { accA[i] = 0ull; accB[i] = 0ull; }

#pragma unroll
        for (int j = 0; j < 16; ++j) {
            int k = lane + 32 * j;
            unsigned long long ha = *(const unsigned long long*)&hA[k];
            unsigned long long hb = *(const unsigned long long*)&hB[k];
#pragma unroll
            for (int i = 0; i < 6; ++i)
                ffma2_dual(accA[i], accB[i], w[i][j], ha, hb);
        }

        // ---- reduce over lanes: xor16, xor8 -> lanes 0-7 hold 8-way partials
        float pA0[6], pA1[6], pB0[6], pB1[6];
#pragma unroll
        for (int i = 0; i < 6; ++i) {
            asm("mov.b64 {%0,%1}, %2;" : "=f"(pA0[i]), "=f"(pA1[i]) : "l"(accA[i]));
            asm("mov.b64 {%0,%1}, %2;" : "=f"(pB0[i]), "=f"(pB1[i]) : "l"(accB[i]));
            pA0[i] += __shfl_xor_sync(0xffffffffu, pA0[i], 16);
            pA1[i] += __shfl_xor_sync(0xffffffffu, pA1[i], 16);
            pB0[i] += __shfl_xor_sync(0xffffffffu, pB0[i], 16);
            pB1[i] += __shfl_xor_sync(0xffffffffu, pB1[i], 16);
            pA0[i] += __shfl_xor_sync(0xffffffffu, pA0[i], 8);
            pA1[i] += __shfl_xor_sync(0xffffffffu, pA1[i], 8);
            pB0[i] += __shfl_xor_sync(0xffffffffu, pB0[i], 8);
            pB1[i] += __shfl_xor_sync(0xffffffffu, pB1[i], 8);
        }
        if (lane < 8) {
#pragma unroll
            for (int i = 0; i < 6; ++i) {
                int cc = 6 * warp + i;
                red[(cc * BPG + 0) * 8 + lane] = pA0[i];
                red[(cc * BPG + 1) * 8 + lane] = pA1[i];
                red[(cc * BPG + 2) * 8 + lane] = pB0[i];
                red[(cc * BPG + 3) * 8 + lane] = pB1[i];
            }
        }
        __syncthreads();

        // ---- gates (64 threads: 16 dims x 4 batches) ----
        if (tid < 64) {
            float gh[3];
#pragma unroll
            for (int g3 = 0; g3 < 3; ++g3) {
                const float* rp = &red[((g3 * 16 + dloc) * BPG + gb) * 8];
                float s = 0.f;
#pragma unroll
                for (int l = 0; l < 8; ++l) s += rp[l];
                gh[g3] = s;
            }
            float r = 1.f / (1.f + __expf(-(gir + gh[0])));
            float z = 1.f / (1.f + __expf(-(giz + gh[1])));
            float n = tanhf(gin + r * (gh[2] + my_bhn));
            float hnew = (1.f - z) * n + z * hold;
            Hn[(d0 + dloc) * BPG + gb] = hnew;
            g_rnn[((size_t)(b0 + gb) * Sm + t) * Dm + d0 + dloc] = hnew;
        }
        __syncthreads();

        // ---- per-group barrier (single monotone counter + poll) ----
        target += GCTA;
        if (tid == 0) {
            __threadfence();
            atomicAdd(cnt, 1u);
            while (ld_acq(cnt) < target) { }
        }
        __syncthreads();
    }
}

// ---------------------------------------------------------------------------
extern "C" void kernel_launch(void* const* d_in, const int* in_sizes, int n_in,
                              void* d_out, int out_size)
{
    const float* x   = (const float*)d_in[0];
    const float* Wi  = (const float*)d_in[1];
    const float* bi  = (const float*)d_in[2];
    const float* Wh  = (const float*)d_in[3];
    const float* bhn = (const float*)d_in[4];
    const float* Wo  = (const float*)d_in[5];
    const float* bo  = (const float*)d_in[6];
    float* out = (float*)d_out;

    void* gi_ptr = nullptr;
    void* rnn_ptr = nullptr;
    cudaGetSymbolAddress(&gi_ptr, g_gi);
    cudaGetSymbolAddress(&rnn_ptr, g_rnn);

    init_state<<<32, 256>>>();

    dim3 g1(G3 / 64, (Bm_ * Sm) / 128);
    sgemm_bias<<<g1, 256>>>(x, Wi, bi, (float*)gi_ptr, Bm_ * Sm, G3, Dm);

    gru_scan<<<NBLK, NTHR>>>(Wh, bhn);

    dim3 g2(Dm / 64, (Bm_ * Sm) / 128);
    sgemm_bias<<<g2, 256>>>((const float*)rnn_ptr, Wo, bo, out, Bm_ * Sm, Dm, Dm);
}